// round 1
// baseline (speedup 1.0000x reference)
#include <cuda_runtime.h>
#include <math.h>

// Problem constants: B=1, C=128, H=W=64 -> N=4096, 4 heads, d=32
#define CCH   128
#define NCOLS 4096
#define NTOT  (CCH * NCOLS)   // 524288
#define NH    4
#define DH    32

// ---------------- scratch (device globals; no allocs allowed) ----------------
__device__ float g_partials[1024];           // 512 sums + 512 sumsqs
__device__ float g_stats[2];                 // mean, rstd
__device__ float g_h [CCH * NCOLS];          // normalized input
__device__ float g_q [CCH * NCOLS];
__device__ float g_k [CCH * NCOLS];
__device__ float g_v [CCH * NCOLS];
__device__ float g_ao[CCH * NCOLS];          // attention output (pre-proj)

// ---------------- GroupNorm stage 1: per-block partial sums ----------------
__global__ void reduce1(const float* __restrict__ x) {
    __shared__ float ss[256];
    __shared__ float sq[256];
    int tid = threadIdx.x;
    int base = blockIdx.x * 1024;
    float s = 0.f, q = 0.f;
#pragma unroll
    for (int j = 0; j < 4; j++) {
        float v = x[base + tid + j * 256];
        s += v; q += v * v;
    }
    ss[tid] = s; sq[tid] = q;
    __syncthreads();
    for (int o = 128; o > 0; o >>= 1) {
        if (tid < o) { ss[tid] += ss[tid + o]; sq[tid] += sq[tid + o]; }
        __syncthreads();
    }
    if (tid == 0) {
        g_partials[blockIdx.x]       = ss[0];
        g_partials[512 + blockIdx.x] = sq[0];
    }
}

// ---------------- GroupNorm stage 2: finalize mean / rstd ----------------
__global__ void reduce2() {
    __shared__ float ss[512];
    __shared__ float sq[512];
    int t = threadIdx.x;
    ss[t] = g_partials[t];
    sq[t] = g_partials[512 + t];
    __syncthreads();
    for (int o = 256; o > 0; o >>= 1) {
        if (t < o) { ss[t] += ss[t + o]; sq[t] += sq[t + o]; }
        __syncthreads();
    }
    if (t == 0) {
        float mean = ss[0] / (float)NTOT;
        float var  = sq[0] / (float)NTOT - mean * mean;
        g_stats[0] = mean;
        g_stats[1] = rsqrtf(var + 1e-5f);
    }
}

// ---------------- normalize + affine ----------------
__global__ void gnorm(const float* __restrict__ x,
                      const float* __restrict__ w,
                      const float* __restrict__ b) {
    float mean = g_stats[0], rstd = g_stats[1];
    int base = blockIdx.x * 1024 + threadIdx.x;
#pragma unroll
    for (int j = 0; j < 4; j++) {
        int i = base + j * 256;
        int c = i >> 12;               // 4096 elems per channel
        g_h[i] = (x[i] - mean) * rstd * w[c] + b[c];
    }
}

// ---------------- SGEMM: C[128,4096] = A[128,128] @ B[128,4096] + bias (+resid)
// 64x64 CTA tile, 4x4 microtile, 256 threads, K split in 32-chunks.
__global__ __launch_bounds__(256) void sgemm(const float* __restrict__ A,
                                             const float* __restrict__ Bm,
                                             const float* __restrict__ bias,
                                             const float* __restrict__ resid,
                                             float* __restrict__ C) {
    __shared__ float sA[32][65];   // [k][m], padded
    __shared__ float sB[32][64];   // [k][n]
    int tid = threadIdx.x;
    int tx = tid & 15, ty = tid >> 4;
    int rowBase = blockIdx.y * 64;
    int colBase = blockIdx.x * 64;

    float acc[4][4];
#pragma unroll
    for (int i = 0; i < 4; i++)
#pragma unroll
        for (int j = 0; j < 4; j++) acc[i][j] = 0.f;

    for (int k0 = 0; k0 < 128; k0 += 32) {
        // load A tile (transpose into [k][m])
        int kk = tid & 31;
#pragma unroll
        for (int r = tid >> 5; r < 64; r += 8)
            sA[kk][r] = A[(rowBase + r) * 128 + k0 + kk];
        // load B tile (natural [k][n])
        int cc = tid & 63;
#pragma unroll
        for (int kr = tid >> 6; kr < 32; kr += 4)
            sB[kr][cc] = Bm[(k0 + kr) * NCOLS + colBase + cc];
        __syncthreads();

#pragma unroll
        for (int k = 0; k < 32; k++) {
            float a[4], b[4];
#pragma unroll
            for (int i = 0; i < 4; i++) a[i] = sA[k][ty * 4 + i];
            float4 bv = *(const float4*)&sB[k][tx * 4];
            b[0] = bv.x; b[1] = bv.y; b[2] = bv.z; b[3] = bv.w;
#pragma unroll
            for (int i = 0; i < 4; i++)
#pragma unroll
                for (int j = 0; j < 4; j++) acc[i][j] += a[i] * b[j];
        }
        __syncthreads();
    }

#pragma unroll
    for (int i = 0; i < 4; i++) {
        int row = rowBase + ty * 4 + i;
        float bs = bias[row];
#pragma unroll
        for (int j = 0; j < 4; j++) {
            int col = colBase + tx * 4 + j;
            float v = acc[i][j] + bs;
            if (resid) v += resid[row * NCOLS + col];
            C[row * NCOLS + col] = v;
        }
    }
}

// ---------------- fused flash attention ----------------
// grid (64 q-tiles, 4 heads), 256 threads.
// thread: qr = tid>>2 (query within tile), sub = tid&3 owns keys [sub*16, sub*16+16)
// of each 64-key tile; online softmax per thread, shfl-merge across the 4 subs.
__global__ __launch_bounds__(256, 2) void attn(const float* __restrict__ Q,
                                               const float* __restrict__ K,
                                               const float* __restrict__ V,
                                               float* __restrict__ O) {
    const int head = blockIdx.y;
    const int q0 = blockIdx.x * 64;
    const int tid = threadIdx.x;
    const int sub = tid & 3;
    const int qr  = tid >> 2;
    const int qcol = q0 + qr;
    const float scale = 0.17677669529663687f;   // 1/sqrt(32)

    __shared__ float sK[32][64];
    __shared__ float sV[32][64];

    const float* Qh = Q + head * DH * NCOLS;
    const float* Kh = K + head * DH * NCOLS;
    const float* Vh = V + head * DH * NCOLS;

    float qv[32];
#pragma unroll
    for (int d = 0; d < DH; d++) qv[d] = Qh[d * NCOLS + qcol] * scale;

    float run_m = -1e30f, run_l = 0.f;
    float acc[32];
#pragma unroll
    for (int d = 0; d < DH; d++) acc[d] = 0.f;

    for (int m0 = 0; m0 < NCOLS; m0 += 64) {
        __syncthreads();
        {
            int cc = tid & 63;
#pragma unroll
            for (int d = tid >> 6; d < DH; d += 4) {
                sK[d][cc] = Kh[d * NCOLS + m0 + cc];
                sV[d][cc] = Vh[d * NCOLS + m0 + cc];
            }
        }
        __syncthreads();

        // S = q . K  for this thread's 16 contiguous keys
        float s[16];
#pragma unroll
        for (int i = 0; i < 16; i++) s[i] = 0.f;
#pragma unroll
        for (int d = 0; d < DH; d++) {
            float qd = qv[d];
            const float4* kp = (const float4*)&sK[d][sub * 16];
            float4 k0v = kp[0], k1v = kp[1], k2v = kp[2], k3v = kp[3];
            s[0]  += qd * k0v.x; s[1]  += qd * k0v.y; s[2]  += qd * k0v.z; s[3]  += qd * k0v.w;
            s[4]  += qd * k1v.x; s[5]  += qd * k1v.y; s[6]  += qd * k1v.z; s[7]  += qd * k1v.w;
            s[8]  += qd * k2v.x; s[9]  += qd * k2v.y; s[10] += qd * k2v.z; s[11] += qd * k2v.w;
            s[12] += qd * k3v.x; s[13] += qd * k3v.y; s[14] += qd * k3v.z; s[15] += qd * k3v.w;
        }

        // online softmax update
        float tmax = s[0];
#pragma unroll
        for (int i = 1; i < 16; i++) tmax = fmaxf(tmax, s[i]);
        float nm = fmaxf(run_m, tmax);
        float corr = __expf(run_m - nm);
        float p[16];
        float ls = 0.f;
#pragma unroll
        for (int i = 0; i < 16; i++) { p[i] = __expf(s[i] - nm); ls += p[i]; }
        run_l = run_l * corr + ls;
        run_m = nm;

        // acc = acc*corr + P . V
#pragma unroll
        for (int d = 0; d < DH; d++) {
            float a = acc[d] * corr;
            const float4* vp = (const float4*)&sV[d][sub * 16];
            float4 v0 = vp[0], v1 = vp[1], v2 = vp[2], v3 = vp[3];
            a += p[0]  * v0.x; a += p[1]  * v0.y; a += p[2]  * v0.z; a += p[3]  * v0.w;
            a += p[4]  * v1.x; a += p[5]  * v1.y; a += p[6]  * v1.z; a += p[7]  * v1.w;
            a += p[8]  * v2.x; a += p[9]  * v2.y; a += p[10] * v2.z; a += p[11] * v2.w;
            a += p[12] * v3.x; a += p[13] * v3.y; a += p[14] * v3.z; a += p[15] * v3.w;
            acc[d] = a;
        }
    }

    // merge the 4 sub-threads of this query (lanes differ in bits 0..1)
#pragma unroll
    for (int off = 1; off <= 2; off <<= 1) {
        float om = __shfl_xor_sync(0xffffffffu, run_m, off);
        float ol = __shfl_xor_sync(0xffffffffu, run_l, off);
        float nm = fmaxf(run_m, om);
        float c1 = __expf(run_m - nm);
        float c2 = __expf(om   - nm);
        run_l = run_l * c1 + ol * c2;
        run_m = nm;
#pragma unroll
        for (int d = 0; d < DH; d++) {
            float oa = __shfl_xor_sync(0xffffffffu, acc[d], off);
            acc[d] = acc[d] * c1 + oa * c2;
        }
    }

    float inv = 1.f / run_l;
    float* Oh = O + head * DH * NCOLS;
#pragma unroll
    for (int j = 0; j < 8; j++) {
        int d = sub * 8 + j;
        Oh[d * NCOLS + qcol] = acc[d] * inv;
    }
}

// ---------------- launch ----------------
extern "C" void kernel_launch(void* const* d_in, const int* in_sizes, int n_in,
                              void* d_out, int out_size) {
    const float* x   = (const float*)d_in[0];
    const float* gnw = (const float*)d_in[1];
    const float* gnb = (const float*)d_in[2];
    const float* qw  = (const float*)d_in[3];
    const float* qb  = (const float*)d_in[4];
    const float* kw  = (const float*)d_in[5];
    const float* kb  = (const float*)d_in[6];
    const float* vw  = (const float*)d_in[7];
    const float* vb  = (const float*)d_in[8];
    const float* pw  = (const float*)d_in[9];
    const float* pb  = (const float*)d_in[10];
    float* out = (float*)d_out;

    float *h_, *q_, *k_, *v_, *ao_;
    cudaGetSymbolAddress((void**)&h_,  g_h);
    cudaGetSymbolAddress((void**)&q_,  g_q);
    cudaGetSymbolAddress((void**)&k_,  g_k);
    cudaGetSymbolAddress((void**)&v_,  g_v);
    cudaGetSymbolAddress((void**)&ao_, g_ao);

    reduce1<<<512, 256>>>(x);
    reduce2<<<1, 512>>>();
    gnorm<<<512, 256>>>(x, gnw, gnb);

    dim3 gg(64, 2);
    sgemm<<<gg, 256>>>(qw, h_, qb, nullptr, q_);
    sgemm<<<gg, 256>>>(kw, h_, kb, nullptr, k_);
    sgemm<<<gg, 256>>>(vw, h_, vb, nullptr, v_);

    dim3 ga(64, 4);
    attn<<<ga, 256>>>(q_, k_, v_, ao_);

    sgemm<<<gg, 256>>>(pw, ao_, pb, x, out);
}